// round 13
// baseline (speedup 1.0000x reference)
#include <cuda_runtime.h>
#include <math.h>
#include <stdint.h>

// ---------------------------------------------------------------------------
// Problem constants
// ---------------------------------------------------------------------------
#define B       1024
#define D       512
#define C       100000
#define TM      128                    // CTA rows
#define TN      128                    // CTA classes
#define NT      ((C + TN - 1) / TN)    // 782 class tiles
#define NTE     (NT * 2)               // 2 col-half partials per class tile
#define KCHUNK  128                    // int8 K elems per chunk (128B rows)
#define NCHUNK  (D / KCHUNK)           // 4
#define SCALE_F 64.0f
#define L2E_64  92.33248261689366f     // 64 * log2(e)

// ArcFace margin constants (margin = 0.5)
#define COS_M  0.8775825618903728f
#define SIN_M  0.47942553860420301f
#define TH_M  (-0.8775825618903728f)
#define MM_M   0.23971276930210151f

// smem: per stage A tile 128x128B (16KB) + B tile 128x128B (16KB)
#define TILE_BYTES  16384
#define STAGE_BYTES (2 * TILE_BYTES)
#define SMEM_BYTES  (1024 + 3 * STAGE_BYTES)   // 99328 -> 2 CTA/SM

// Scratch (__device__ globals; no allocations allowed)
__device__ int8_t g_Ei8[(size_t)B * D];
__device__ int8_t g_Wi8[(size_t)C * D];
__device__ float  g_einv[B];      // 1/||e||  (exact fp32, for label term)
__device__ float  g_winv[C];      // 1/||w||
__device__ float  g_fe[B];        // s_e * einv   (quant-scale folded)
__device__ float  g_fw[C];        // s_w * winv
__device__ float  g_ldot[B];
__device__ float  g_psum[(size_t)B * NTE];
__device__ float  g_nll[B];

// ---------------------------------------------------------------------------
// PTX helpers (base ISA only -- nothing gated on sm_103a)
// ---------------------------------------------------------------------------
__device__ __forceinline__ uint32_t smem_u32(const void* p) {
    uint32_t a;
    asm("{ .reg .u64 t; cvta.to.shared.u64 t, %1; cvt.u32.u64 %0, t; }"
        : "=r"(a) : "l"(p));
    return a;
}
__device__ __forceinline__ void cp16(uint32_t dst, const void* src) {
    asm volatile("cp.async.cg.shared.global [%0], [%1], 16;"
                 :: "r"(dst), "l"(src));
}
__device__ __forceinline__ void cp_commit() {
    asm volatile("cp.async.commit_group;" ::: "memory");
}
template <int N> __device__ __forceinline__ void cp_wait() {
    asm volatile("cp.async.wait_group %0;" :: "n"(N) : "memory");
}
__device__ __forceinline__ void st_zero16(uint32_t dst) {
    asm volatile("st.shared.v4.u32 [%0], {%1, %1, %1, %1};"
                 :: "r"(dst), "r"(0u) : "memory");
}
__device__ __forceinline__ void ldsm4(uint32_t* r, uint32_t addr) {
    asm volatile("ldmatrix.sync.aligned.m8n8.x4.shared.b16 {%0,%1,%2,%3}, [%4];"
                 : "=r"(r[0]), "=r"(r[1]), "=r"(r[2]), "=r"(r[3]) : "r"(addr));
}
// int8 m16n8k32 IMMA; s32 acc in-place
__device__ __forceinline__ void mma_s8(int* d, const uint32_t* a,
                                       const uint32_t* b) {
    asm volatile(
        "mma.sync.aligned.m16n8k32.row.col.s32.s8.s8.s32 "
        "{%0,%1,%2,%3}, {%4,%5,%6,%7}, {%8,%9}, {%0,%1,%2,%3};"
        : "+r"(d[0]), "+r"(d[1]), "+r"(d[2]), "+r"(d[3])
        : "r"(a[0]), "r"(a[1]), "r"(a[2]), "r"(a[3]), "r"(b[0]), "r"(b[1]));
}
__device__ __forceinline__ float ex2(float x) {
    float r;
    asm("ex2.approx.ftz.f32 %0, %1;" : "=f"(r) : "f"(x));
    return r;
}

// ---------------------------------------------------------------------------
// Norm + int8-quantize kernels (one warp per row, single pass over data)
// ---------------------------------------------------------------------------
__global__ void e_conv_kernel(const float* __restrict__ E) {
    int warp = (blockIdx.x * blockDim.x + threadIdx.x) >> 5;
    int lane = threadIdx.x & 31;
    if (warp >= B) return;
    const float* row = E + (size_t)warp * D;
    float4 v[4];
    float ss = 0.f, amax = 0.f;
    #pragma unroll
    for (int j = 0; j < 4; j++) {
        v[j] = *(const float4*)(row + (j * 32 + lane) * 4);
        ss = fmaf(v[j].x, v[j].x, fmaf(v[j].y, v[j].y,
             fmaf(v[j].z, v[j].z, fmaf(v[j].w, v[j].w, ss))));
        amax = fmaxf(amax, fmaxf(fmaxf(fabsf(v[j].x), fabsf(v[j].y)),
                                 fmaxf(fabsf(v[j].z), fabsf(v[j].w))));
    }
    #pragma unroll
    for (int o = 16; o > 0; o >>= 1) {
        ss  += __shfl_xor_sync(0xffffffffu, ss, o);
        amax = fmaxf(amax, __shfl_xor_sync(0xffffffffu, amax, o));
    }
    float qs = (amax > 0.f) ? (127.f / amax) : 0.f;
    char4* dst = (char4*)(g_Ei8 + (size_t)warp * D);
    #pragma unroll
    for (int j = 0; j < 4; j++) {
        char4 q;
        q.x = (char)__float2int_rn(v[j].x * qs);
        q.y = (char)__float2int_rn(v[j].y * qs);
        q.z = (char)__float2int_rn(v[j].z * qs);
        q.w = (char)__float2int_rn(v[j].w * qs);
        dst[j * 32 + lane] = q;
    }
    if (lane == 0) {
        float einv = 1.0f / fmaxf(sqrtf(ss), 1e-12f);
        g_einv[warp] = einv;
        g_fe[warp]   = (amax / 127.f) * einv;
    }
}

__global__ void w_conv_kernel(const float* __restrict__ W) {
    int warp = (blockIdx.x * blockDim.x + threadIdx.x) >> 5;
    int lane = threadIdx.x & 31;
    if (warp >= C) return;
    const float* row = W + (size_t)warp * D;
    float4 v[4];
    float ss = 0.f, amax = 0.f;
    #pragma unroll
    for (int j = 0; j < 4; j++) {
        v[j] = *(const float4*)(row + (j * 32 + lane) * 4);
        ss = fmaf(v[j].x, v[j].x, fmaf(v[j].y, v[j].y,
             fmaf(v[j].z, v[j].z, fmaf(v[j].w, v[j].w, ss))));
        amax = fmaxf(amax, fmaxf(fmaxf(fabsf(v[j].x), fabsf(v[j].y)),
                                 fmaxf(fabsf(v[j].z), fabsf(v[j].w))));
    }
    #pragma unroll
    for (int o = 16; o > 0; o >>= 1) {
        ss  += __shfl_xor_sync(0xffffffffu, ss, o);
        amax = fmaxf(amax, __shfl_xor_sync(0xffffffffu, amax, o));
    }
    float qs = (amax > 0.f) ? (127.f / amax) : 0.f;
    char4* dst = (char4*)(g_Wi8 + (size_t)warp * D);
    #pragma unroll
    for (int j = 0; j < 4; j++) {
        char4 q;
        q.x = (char)__float2int_rn(v[j].x * qs);
        q.y = (char)__float2int_rn(v[j].y * qs);
        q.z = (char)__float2int_rn(v[j].z * qs);
        q.w = (char)__float2int_rn(v[j].w * qs);
        dst[j * 32 + lane] = q;
    }
    if (lane == 0) {
        float winv = 1.0f / fmaxf(sqrtf(ss), 1e-12f);
        g_winv[warp] = winv;
        g_fw[warp]   = (amax / 127.f) * winv;
    }
}

__global__ void label_dot_kernel(const float* __restrict__ E,
                                 const float* __restrict__ W,
                                 const int* __restrict__ labels) {
    int warp = (blockIdx.x * blockDim.x + threadIdx.x) >> 5;
    int lane = threadIdx.x & 31;
    if (warp >= B) return;
    int lab = labels[warp];
    const float* e = E + (size_t)warp * D;
    const float* w = W + (size_t)lab * D;
    float s = 0.f;
    #pragma unroll
    for (int i = 0; i < D / 32; i++) s = fmaf(e[lane + i * 32], w[lane + i * 32], s);
    #pragma unroll
    for (int o = 16; o > 0; o >>= 1) s += __shfl_xor_sync(0xffffffffu, s, o);
    if (lane == 0) g_ldot[warp] = s;
}

// ---------------------------------------------------------------------------
// Main: int8 IMMA GEMM (128x128 CTA, 4 warps of 64x64, ldmatrix, XOR swizzle)
// + fused fixed-max softmax partials (max == SCALE == 64).
// grid (8, 782) x-major: W tile HBM-read once, L2-hit by the other 7 rowTiles.
// ---------------------------------------------------------------------------
__global__ void __launch_bounds__(128, 2)
gemm_tc_kernel(void) {
    extern __shared__ float smem[];
    float* fe_s = smem;                // 128: s_e * einv * 64*log2e
    float* fw_s = smem + 128;          // 128: s_w * winv
    char*  sdata = (char*)(smem + 256);

    const int tid  = threadIdx.x;
    const int wid  = tid >> 5;
    const int lane = tid & 31;
    const int wm   = wid >> 1;
    const int wn   = wid & 1;
    const int qid  = lane >> 2;
    const int ql   = lane & 3;
    const int rowBase   = blockIdx.x * TM;
    const int classBase = blockIdx.y * TN;

    fe_s[tid] = g_fe[rowBase + tid] * L2E_64;
    fw_s[tid] = (classBase + tid < C) ? g_fw[classBase + tid] : 0.0f;

    int acc[4][8][4];
    #pragma unroll
    for (int mt = 0; mt < 4; mt++)
        #pragma unroll
        for (int nt = 0; nt < 8; nt++)
            #pragma unroll
            for (int c = 0; c < 4; c++) acc[mt][nt][c] = 0;

    const uint32_t s0 = smem_u32(sdata);

    // --- chunk loader: A 16KB + B 16KB, XOR-swizzled 16B units ---
    auto load_chunk = [&](int k, int st) {
        const uint32_t sa  = s0 + st * STAGE_BYTES;
        const uint32_t sb  = sa + TILE_BYTES;
        const int      kof = k * KCHUNK;
        const int8_t*  Ep  = g_Ei8 + (size_t)rowBase * D + kof;
        #pragma unroll
        for (int i = 0; i < 8; i++) {
            int idx = tid + i * 128;           // 0..1023
            int r = idx >> 3, c = idx & 7;
            uint32_t dst = sa + r * 128 + ((c ^ (r & 7)) << 4);
            cp16(dst, Ep + (size_t)r * D + c * 16);
        }
        #pragma unroll
        for (int i = 0; i < 8; i++) {
            int idx = tid + i * 128;
            int r = idx >> 3, c = idx & 7;
            int cls = classBase + r;
            uint32_t dst = sb + r * 128 + ((c ^ (r & 7)) << 4);
            if (cls < C) cp16(dst, g_Wi8 + (size_t)cls * D + kof + c * 16);
            else         st_zero16(dst);
        }
        cp_commit();
    };

    // ldmatrix per-lane address components (identical pattern to fp16 k16,
    // with 16B k-halves of the 32B k-step)
    const int aRow = (lane & 7) + ((lane >> 3) & 1) * 8;   // row within 16
    const int kgA  = lane >> 4;                            // k 16B-half
    const int bRow = (lane & 7) + (lane >> 4) * 8;         // class row within 16
    const int kgB  = (lane >> 3) & 1;

    auto compute_chunk = [&](int st) {
        const uint32_t sa = s0 + st * STAGE_BYTES;
        const uint32_t sb = sa + TILE_BYTES;
        #pragma unroll
        for (int ks = 0; ks < 4; ks++) {       // 4 x k32 = 128
            uint32_t a[4][4], bb[4][4];
            const int cA = ks * 2 + kgA;
            const int cB = ks * 2 + kgB;
            const uint32_t swA = (uint32_t)((cA ^ (lane & 7)) << 4);
            const uint32_t swB = (uint32_t)((cB ^ (lane & 7)) << 4);
            #pragma unroll
            for (int mt = 0; mt < 4; mt++)
                ldsm4(a[mt], sa + (wm * 64 + mt * 16 + aRow) * 128 + swA);
            #pragma unroll
            for (int ntp = 0; ntp < 4; ntp++)
                ldsm4(bb[ntp], sb + (wn * 64 + ntp * 16 + bRow) * 128 + swB);
            #pragma unroll
            for (int mt = 0; mt < 4; mt++)
                #pragma unroll
                for (int nt = 0; nt < 8; nt++) {
                    uint32_t bfrag[2] = { bb[nt >> 1][(nt & 1) * 2],
                                          bb[nt >> 1][(nt & 1) * 2 + 1] };
                    mma_s8(acc[mt][nt], a[mt], bfrag);
                }
        }
    };

    load_chunk(0, 0);
    load_chunk(1, 1);
    load_chunk(2, 2);

    for (int k = 0; k < NCHUNK; k++) {
        const int st = k % 3;
        if (k < NCHUNK - 2)       cp_wait<2>();
        else if (k == NCHUNK - 2) cp_wait<1>();
        else                      cp_wait<0>();
        __syncthreads();
        compute_chunk(st);
        if (k + 3 < NCHUNK) {
            __syncthreads();              // all warps done reading stage st
            load_chunk(k + 3, st);
        }
    }

    // --- epilogue: partial Σ exp(l - 64), fixed max (l <= 64 always) ---
    // exact I2F: |acc| <= 127*127*512 = 8.26M < 2^24
    const int tileIdx = blockIdx.y * 2 + wn;
    #pragma unroll
    for (int mt = 0; mt < 4; mt++) {
        #pragma unroll
        for (int h = 0; h < 2; h++) {
            const int   rloc = wm * 64 + mt * 16 + qid + h * 8;
            const float fe   = fe_s[rloc];
            float s = 0.f;
            #pragma unroll
            for (int nt = 0; nt < 8; nt++) {
                #pragma unroll
                for (int c = 0; c < 2; c++) {
                    float fw = fw_s[wn * 64 + nt * 8 + ql * 2 + c];
                    float u  = (float)acc[mt][nt][h * 2 + c] * fe;
                    s += ex2(fmaf(u, fw, -L2E_64));
                }
            }
            s += __shfl_xor_sync(0xffffffffu, s, 1);
            s += __shfl_xor_sync(0xffffffffu, s, 2);
            if (ql == 0)
                g_psum[(size_t)(rowBase + rloc) * NTE + tileIdx] = s;
        }
    }
}

// ---------------------------------------------------------------------------
// Finalize stage 1: one warp per row sums NTE partials + label correction.
// ---------------------------------------------------------------------------
__global__ void finalize_rows_kernel(const int* __restrict__ labels) {
    int gw   = (blockIdx.x * blockDim.x + threadIdx.x) >> 5;
    int lane = threadIdx.x & 31;
    if (gw >= B) return;
    const float* ps = g_psum + (size_t)gw * NTE;

    float s = 0.f;
    for (int t = lane; t < NTE; t += 32) s += ps[t];
    #pragma unroll
    for (int o = 16; o > 0; o >>= 1) s += __shfl_xor_sync(0xffffffffu, s, o);

    if (lane == 0) {
        int lab = labels[gw];
        float cosl = g_ldot[gw] * g_einv[gw] * g_winv[lab];
        float c2   = 1.0f - cosl * cosl;
        float sine = sqrtf(fminf(fmaxf(c2, 0.f), 1.f));
        float phi  = cosl * COS_M - sine * SIN_M;
        phi = (cosl > TH_M) ? phi : (cosl - MM_M);

        float lo = SCALE_F * cosl;   // original label logit
        float ln = SCALE_F * phi;    // margined logit
        s += expf(ln - SCALE_F) - expf(lo - SCALE_F);
        // logZ = 64 + log(s); nll = logZ - ln
        g_nll[gw] = SCALE_F + logf(s) - ln;
    }
}

__global__ void finalize_reduce_kernel(float* __restrict__ out) {
    __shared__ float red[B];
    int b = threadIdx.x;
    red[b] = g_nll[b];
    __syncthreads();
    #pragma unroll
    for (int o = B / 2; o > 0; o >>= 1) {
        if (b < o) red[b] += red[b + o];
        __syncthreads();
    }
    if (b == 0) out[0] = red[0] / (float)B;
}

// ---------------------------------------------------------------------------
extern "C" void kernel_launch(void* const* d_in, const int* in_sizes, int n_in,
                              void* d_out, int out_size) {
    const float* E      = (const float*)d_in[0];
    const float* W      = (const float*)d_in[1];
    const int*   labels = (const int*)d_in[2];
    float*       out    = (float*)d_out;

    cudaFuncSetAttribute(gemm_tc_kernel,
                         cudaFuncAttributeMaxDynamicSharedMemorySize, SMEM_BYTES);

    e_conv_kernel<<<(B * 32) / 256, 256>>>(E);
    w_conv_kernel<<<(C * 32 + 255) / 256, 256>>>(W);
    label_dot_kernel<<<(B * 32) / 256, 256>>>(E, W, labels);

    dim3 grid(B / TM, NT);   // (8, 782), x-major => W-tile L2 reuse
    gemm_tc_kernel<<<grid, 128, SMEM_BYTES>>>();

    finalize_rows_kernel<<<(B * 32 + 255) / 256, 256>>>(labels);
    finalize_reduce_kernel<<<1, B>>>(out);
}

// round 14
// speedup vs baseline: 2.5200x; 2.5200x over previous
#include <cuda_runtime.h>
#include <cuda_fp16.h>
#include <math.h>
#include <stdint.h>

// ---------------------------------------------------------------------------
// Problem constants
// ---------------------------------------------------------------------------
#define B       1024
#define D       512
#define C       100000
#define TM      128                    // CTA rows
#define TN      128                    // CTA classes
#define NT      ((C + TN - 1) / TN)    // 782 class tiles
#define NTE     (NT * 2)               // 2 col-half partials per class tile
#define KCHUNK  64                     // fp16 K elems per chunk (128B rows)
#define NCHUNK  (D / KCHUNK)           // 8
#define SCALE_F 64.0f
#define L2E_64  92.33248261689366f     // 64 * log2(e)

// ArcFace margin constants (margin = 0.5)
#define COS_M  0.8775825618903728f
#define SIN_M  0.47942553860420301f
#define TH_M  (-0.8775825618903728f)
#define MM_M   0.23971276930210151f

// smem: per stage A tile 128x128B (16KB) + B tile 128x128B (16KB)
#define TILE_BYTES  16384
#define STAGE_BYTES (2 * TILE_BYTES)
#define SMEM_BYTES  (1024 + 3 * STAGE_BYTES)   // 99328 -> 2 CTA/SM

// Scratch (__device__ globals; no allocations allowed)
__device__ __half g_Eh[(size_t)B * D];
__device__ __half g_Wh[(size_t)C * D];
__device__ float  g_einv[B];
__device__ float  g_winv[C];
__device__ float  g_ldot[B];
__device__ float  g_psum[(size_t)B * NTE];
__device__ float  g_nll[B];

// ---------------------------------------------------------------------------
// PTX helpers (base ISA only -- nothing gated on sm_103a)
// ---------------------------------------------------------------------------
__device__ __forceinline__ uint32_t smem_u32(const void* p) {
    uint32_t a;
    asm("{ .reg .u64 t; cvta.to.shared.u64 t, %1; cvt.u32.u64 %0, t; }"
        : "=r"(a) : "l"(p));
    return a;
}
__device__ __forceinline__ void cp16(uint32_t dst, const void* src) {
    asm volatile("cp.async.cg.shared.global [%0], [%1], 16;"
                 :: "r"(dst), "l"(src));
}
__device__ __forceinline__ void cp_commit() {
    asm volatile("cp.async.commit_group;" ::: "memory");
}
template <int N> __device__ __forceinline__ void cp_wait() {
    asm volatile("cp.async.wait_group %0;" :: "n"(N) : "memory");
}
__device__ __forceinline__ void st_zero16(uint32_t dst) {
    asm volatile("st.shared.v4.u32 [%0], {%1, %1, %1, %1};"
                 :: "r"(dst), "r"(0u) : "memory");
}
__device__ __forceinline__ void ldsm4(uint32_t* r, uint32_t addr) {
    asm volatile("ldmatrix.sync.aligned.m8n8.x4.shared.b16 {%0,%1,%2,%3}, [%4];"
                 : "=r"(r[0]), "=r"(r[1]), "=r"(r[2]), "=r"(r[3]) : "r"(addr));
}
__device__ __forceinline__ void mma_f16(float* d, const uint32_t* a,
                                        const uint32_t* b) {
    asm volatile(
        "mma.sync.aligned.m16n8k16.row.col.f32.f16.f16.f32 "
        "{%0,%1,%2,%3}, {%4,%5,%6,%7}, {%8,%9}, {%0,%1,%2,%3};"
        : "+f"(d[0]), "+f"(d[1]), "+f"(d[2]), "+f"(d[3])
        : "r"(a[0]), "r"(a[1]), "r"(a[2]), "r"(a[3]), "r"(b[0]), "r"(b[1]));
}
__device__ __forceinline__ float ex2(float x) {
    float r;
    asm("ex2.approx.ftz.f32 %0, %1;" : "=f"(r) : "f"(x));
    return r;
}

// ---------------------------------------------------------------------------
// Norm + fp16-convert kernels (one warp per row, single fused pass)
// ---------------------------------------------------------------------------
__global__ void e_conv_kernel(const float* __restrict__ E) {
    int warp = (blockIdx.x * blockDim.x + threadIdx.x) >> 5;
    int lane = threadIdx.x & 31;
    if (warp >= B) return;
    const float* row = E + (size_t)warp * D;
    __half2* dst = (__half2*)(g_Eh + (size_t)warp * D);
    float ss = 0.f;
    #pragma unroll
    for (int j = 0; j < 4; j++) {
        float4 v = *(const float4*)(row + (j * 32 + lane) * 4);
        ss = fmaf(v.x, v.x, fmaf(v.y, v.y, fmaf(v.z, v.z, fmaf(v.w, v.w, ss))));
        dst[(j * 32 + lane) * 2]     = __floats2half2_rn(v.x, v.y);
        dst[(j * 32 + lane) * 2 + 1] = __floats2half2_rn(v.z, v.w);
    }
    #pragma unroll
    for (int o = 16; o > 0; o >>= 1) ss += __shfl_xor_sync(0xffffffffu, ss, o);
    if (lane == 0) g_einv[warp] = 1.0f / fmaxf(sqrtf(ss), 1e-12f);
}

__global__ void w_conv_kernel(const float* __restrict__ W) {
    int warp = (blockIdx.x * blockDim.x + threadIdx.x) >> 5;
    int lane = threadIdx.x & 31;
    if (warp >= C) return;
    const float* row = W + (size_t)warp * D;
    __half2* dst = (__half2*)(g_Wh + (size_t)warp * D);
    float ss = 0.f;
    #pragma unroll
    for (int j = 0; j < 4; j++) {
        float4 v = *(const float4*)(row + (j * 32 + lane) * 4);
        ss = fmaf(v.x, v.x, fmaf(v.y, v.y, fmaf(v.z, v.z, fmaf(v.w, v.w, ss))));
        dst[(j * 32 + lane) * 2]     = __floats2half2_rn(v.x, v.y);
        dst[(j * 32 + lane) * 2 + 1] = __floats2half2_rn(v.z, v.w);
    }
    #pragma unroll
    for (int o = 16; o > 0; o >>= 1) ss += __shfl_xor_sync(0xffffffffu, ss, o);
    if (lane == 0) g_winv[warp] = 1.0f / fmaxf(sqrtf(ss), 1e-12f);
}

__global__ void label_dot_kernel(const float* __restrict__ E,
                                 const float* __restrict__ W,
                                 const int* __restrict__ labels) {
    int warp = (blockIdx.x * blockDim.x + threadIdx.x) >> 5;
    int lane = threadIdx.x & 31;
    if (warp >= B) return;
    int lab = labels[warp];
    const float* e = E + (size_t)warp * D;
    const float* w = W + (size_t)lab * D;
    float s = 0.f;
    #pragma unroll
    for (int i = 0; i < D / 32; i++) s = fmaf(e[lane + i * 32], w[lane + i * 32], s);
    #pragma unroll
    for (int o = 16; o > 0; o >>= 1) s += __shfl_xor_sync(0xffffffffu, s, o);
    if (lane == 0) g_ldot[warp] = s;
}

// ---------------------------------------------------------------------------
// Main: fp16 mma.sync GEMM. 128x128 CTA tile, 256 threads / 8 warps of 32x64
// (4 warps per SMSP for latency hiding), 3-stage cp.async pipeline with ONE
// __syncthreads per chunk (load target = stage freed in the previous iter,
// protected by this iter's barrier). Fused fixed-max softmax partials.
// grid (8, 782) x-major: W tile HBM-read once, L2-hit by the other 7 rowTiles.
// ---------------------------------------------------------------------------
__global__ void __launch_bounds__(256, 2)
gemm_tc_kernel(void) {
    extern __shared__ float smem[];
    float* einv_s = smem;              // 128: einv * 64*log2e
    float* winv_s = smem + 128;        // 128
    char*  sdata  = (char*)(smem + 256);

    const int tid  = threadIdx.x;
    const int wid  = tid >> 5;
    const int lane = tid & 31;
    const int wm   = wid >> 1;         // 0..3 : 32-row slice
    const int wn   = wid & 1;          // 0..1 : 64-col half
    const int qid  = lane >> 2;        // 0..7
    const int ql   = lane & 3;         // 0..3
    const int rowBase   = blockIdx.x * TM;
    const int classBase = blockIdx.y * TN;

    if (tid < 128) {
        einv_s[tid] = g_einv[rowBase + tid] * L2E_64;
        winv_s[tid] = (classBase + tid < C) ? g_winv[classBase + tid] : 0.0f;
    }

    float acc[2][8][4];
    #pragma unroll
    for (int mt = 0; mt < 2; mt++)
        #pragma unroll
        for (int nt = 0; nt < 8; nt++)
            #pragma unroll
            for (int c = 0; c < 4; c++) acc[mt][nt][c] = 0.f;

    const uint32_t s0 = smem_u32(sdata);

    // --- chunk loader: A 16KB + B 16KB, XOR-swizzled 16B units, 4+4/thread ---
    auto load_chunk = [&](int k, int st) {
        const uint32_t sa  = s0 + st * STAGE_BYTES;
        const uint32_t sb  = sa + TILE_BYTES;
        const int      kof = k * KCHUNK;
        const __half*  Ep  = g_Eh + (size_t)rowBase * D + kof;
        #pragma unroll
        for (int i = 0; i < 4; i++) {
            int idx = tid + i * 256;           // 0..1023
            int r = idx >> 3, c = idx & 7;
            uint32_t dst = sa + r * 128 + ((c ^ (r & 7)) << 4);
            cp16(dst, Ep + (size_t)r * D + c * 8);
        }
        #pragma unroll
        for (int i = 0; i < 4; i++) {
            int idx = tid + i * 256;
            int r = idx >> 3, c = idx & 7;
            int cls = classBase + r;
            uint32_t dst = sb + r * 128 + ((c ^ (r & 7)) << 4);
            if (cls < C) cp16(dst, g_Wh + (size_t)cls * D + kof + c * 8);
            else         st_zero16(dst);
        }
        cp_commit();
    };

    // ldmatrix per-lane address components
    const int aRow = (lane & 7) + ((lane >> 3) & 1) * 8;   // row within 16
    const int kgA  = lane >> 4;                            // k half
    const int bRow = (lane & 7) + (lane >> 4) * 8;         // row within 16
    const int kgB  = (lane >> 3) & 1;

    auto compute_chunk = [&](int st) {
        const uint32_t sa = s0 + st * STAGE_BYTES;
        const uint32_t sb = sa + TILE_BYTES;
        #pragma unroll
        for (int ks = 0; ks < 4; ks++) {
            uint32_t a[2][4], bb[4][4];
            const int cA = ks * 2 + kgA;
            const int cB = ks * 2 + kgB;
            const uint32_t swA = (uint32_t)((cA ^ (lane & 7)) << 4);
            const uint32_t swB = (uint32_t)((cB ^ (lane & 7)) << 4);
            #pragma unroll
            for (int mt = 0; mt < 2; mt++)
                ldsm4(a[mt], sa + (wm * 32 + mt * 16 + aRow) * 128 + swA);
            #pragma unroll
            for (int ntp = 0; ntp < 4; ntp++)
                ldsm4(bb[ntp], sb + (wn * 64 + ntp * 16 + bRow) * 128 + swB);
            #pragma unroll
            for (int mt = 0; mt < 2; mt++)
                #pragma unroll
                for (int nt = 0; nt < 8; nt++) {
                    uint32_t bfrag[2] = { bb[nt >> 1][(nt & 1) * 2],
                                          bb[nt >> 1][(nt & 1) * 2 + 1] };
                    mma_f16(acc[mt][nt], a[mt], bfrag);
                }
        }
    };

    // prologue: 2 chunks in flight, one stage left empty
    load_chunk(0, 0);
    load_chunk(1, 1);

    for (int k = 0; k < NCHUNK; k++) {
        if (k < NCHUNK - 1) cp_wait<1>();   // chunk k landed (k+1 may fly)
        else                cp_wait<0>();
        __syncthreads();                    // all warps done with chunk k-1's stage
        if (k + 2 < NCHUNK) load_chunk(k + 2, (k + 2) % 3);
        compute_chunk(k % 3);
    }

    // --- epilogue: partial Σ exp(l - 64), fixed max (l <= 64 always) ---
    const int tileIdx = blockIdx.y * 2 + wn;
    #pragma unroll
    for (int mt = 0; mt < 2; mt++) {
        #pragma unroll
        for (int h = 0; h < 2; h++) {
            const int   rloc = wm * 32 + mt * 16 + qid + h * 8;
            const float ew   = einv_s[rloc];
            float s = 0.f;
            #pragma unroll
            for (int nt = 0; nt < 8; nt++) {
                #pragma unroll
                for (int c = 0; c < 2; c++) {
                    float wv = winv_s[wn * 64 + nt * 8 + ql * 2 + c];
                    float u  = acc[mt][nt][h * 2 + c] * ew;
                    s += ex2(fmaf(u, wv, -L2E_64));
                }
            }
            s += __shfl_xor_sync(0xffffffffu, s, 1);
            s += __shfl_xor_sync(0xffffffffu, s, 2);
            if (ql == 0)
                g_psum[(size_t)(rowBase + rloc) * NTE + tileIdx] = s;
        }
    }
}

// ---------------------------------------------------------------------------
// Finalize stage 1: one warp per row sums NTE partials + label correction.
// ---------------------------------------------------------------------------
__global__ void finalize_rows_kernel(const int* __restrict__ labels) {
    int gw   = (blockIdx.x * blockDim.x + threadIdx.x) >> 5;
    int lane = threadIdx.x & 31;
    if (gw >= B) return;
    const float* ps = g_psum + (size_t)gw * NTE;

    float s = 0.f;
    for (int t = lane; t < NTE; t += 32) s += ps[t];
    #pragma unroll
    for (int o = 16; o > 0; o >>= 1) s += __shfl_xor_sync(0xffffffffu, s, o);

    if (lane == 0) {
        int lab = labels[gw];
        float cosl = g_ldot[gw] * g_einv[gw] * g_winv[lab];
        float c2   = 1.0f - cosl * cosl;
        float sine = sqrtf(fminf(fmaxf(c2, 0.f), 1.f));
        float phi  = cosl * COS_M - sine * SIN_M;
        phi = (cosl > TH_M) ? phi : (cosl - MM_M);

        float lo = SCALE_F * cosl;   // original label logit
        float ln = SCALE_F * phi;    // margined logit
        s += expf(ln - SCALE_F) - expf(lo - SCALE_F);
        // logZ = 64 + log(s); nll = logZ - ln
        g_nll[gw] = SCALE_F + logf(s) - ln;
    }
}

__global__ void finalize_reduce_kernel(float* __restrict__ out) {
    __shared__ float red[B];
    int b = threadIdx.x;
    red[b] = g_nll[b];
    __syncthreads();
    #pragma unroll
    for (int o = B / 2; o > 0; o >>= 1) {
        if (b < o) red[b] += red[b + o];
        __syncthreads();
    }
    if (b == 0) out[0] = red[0] / (float)B;
}

// ---------------------------------------------------------------------------
extern "C" void kernel_launch(void* const* d_in, const int* in_sizes, int n_in,
                              void* d_out, int out_size) {
    const float* E      = (const float*)d_in[0];
    const float* W      = (const float*)d_in[1];
    const int*   labels = (const int*)d_in[2];
    float*       out    = (float*)d_out;

    cudaFuncSetAttribute(gemm_tc_kernel,
                         cudaFuncAttributeMaxDynamicSharedMemorySize, SMEM_BYTES);

    e_conv_kernel<<<(B * 32) / 256, 256>>>(E);
    w_conv_kernel<<<(C * 32 + 255) / 256, 256>>>(W);
    label_dot_kernel<<<(B * 32) / 256, 256>>>(E, W, labels);

    dim3 grid(B / TM, NT);   // (8, 782), x-major => W-tile L2 reuse
    gemm_tc_kernel<<<grid, 256, SMEM_BYTES>>>();

    finalize_rows_kernel<<<(B * 32 + 255) / 256, 256>>>(labels);
    finalize_reduce_kernel<<<1, B>>>(out);
}